// round 1
// baseline (speedup 1.0000x reference)
#include <cuda_runtime.h>

// Cone-beam flat-panel forward projector.
// vol: [256,256,256] fp32 (z,y,x; x fastest). out: [16,64,384] fp32.

#define Wv 256
#define Hv 256
#define Dv 256
#define NCOL 384
#define NROW 64
#define NVIEW 16
#define NSAMP 256

__device__ __forceinline__ float fetchv(const float* __restrict__ vol,
                                        int z, int y, int x) {
    if ((unsigned)x < (unsigned)Wv && (unsigned)y < (unsigned)Hv &&
        (unsigned)z < (unsigned)Dv) {
        return __ldg(vol + ((z << 16) | (y << 8) | x));
    }
    return 0.0f;
}

__global__ void __launch_bounds__(256)
proj_kernel(const float* __restrict__ vol,
            const float* __restrict__ angles,
            float* __restrict__ out) {
    const int idx = blockIdx.x * blockDim.x + threadIdx.x;
    const int total = NVIEW * NROW * NCOL;
    if (idx >= total) return;

    const int col  = idx % NCOL;
    const int tmp  = idx / NCOL;
    const int row  = tmp % NROW;
    const int view = tmp / NROW;

    const float DET_U = 1.2f, DET_V = 1.2f;
    const float ISO = 500.0f, SDD = 1000.0f;
    const float RAY_LEN = 1.7320508075688772f * 256.0f;  // sqrt(3)*256
    const float DT = RAY_LEN / (float)NSAMP;             // sqrt(3)

    const float beta = angles[view];
    float cb, sb;
    __sincosf(beta, &sb, &cb);   // fast-math variant; beta in [0,2pi), plenty accurate
    // recompute precisely to be safe on the 1e-3 gate:
    cb = cosf(beta);
    sb = sinf(beta);

    const float u = ((float)col - NCOL * 0.5f + 0.5f) * DET_U;
    const float v = ((float)row - NROW * 0.5f + 0.5f) * DET_V;

    // source
    const float sx = ISO * cb;
    const float sy = ISO * sb;
    const float sz = 0.0f;
    // detector point - source
    float dx = -(SDD - ISO) * cb - u * sb - sx;
    float dy = -(SDD - ISO) * sb + u * cb - sy;
    float dz = v - sz;
    const float inv = rsqrtf(dx * dx + dy * dy + dz * dz);
    dx *= inv; dy *= inv; dz *= inv;

    const float t0 = ISO - RAY_LEN * 0.5f + 0.5f * DT;

    // Exact slab clip: a sample contributes 0 unless every voxel coordinate is
    // in (-1, 256), i.e. p_axis in (-128.5, 128.5). The contributing set along
    // the ray is the slab-intersection interval.
    float tmin = -1e30f, tmax = 1e30f;
    {
        const float s0[3] = {sx, sy, sz};
        const float dd[3] = {dx, dy, dz};
        #pragma unroll
        for (int a = 0; a < 3; ++a) {
            if (fabsf(dd[a]) > 1e-12f) {
                const float r  = 1.0f / dd[a];
                const float ta = (-128.5f - s0[a]) * r;
                const float tb = ( 128.5f - s0[a]) * r;
                tmin = fmaxf(tmin, fminf(ta, tb));
                tmax = fminf(tmax, fmaxf(ta, tb));
            } else if (s0[a] <= -128.5f || s0[a] >= 128.5f) {
                tmax = tmin - 1.0f;  // empty
            }
        }
    }
    // widen by one sample against fp rounding; skipped samples are provably 0
    int s_lo = (int)floorf((tmin - t0) / DT);
    int s_hi = (int)ceilf((tmax - t0) / DT) + 1;
    s_lo = max(s_lo, 0);
    s_hi = min(s_hi, NSAMP - 1);

    float acc = 0.0f;
    #pragma unroll 4
    for (int s = s_lo; s <= s_hi; ++s) {
        const float t = fmaf((float)s, DT, t0);
        const float x = fmaf(t, dx, sx) + 127.5f;
        const float y = fmaf(t, dy, sy) + 127.5f;
        const float z = fmaf(t, dz, sz) + 127.5f;

        const float xf = floorf(x), yf = floorf(y), zf = floorf(z);
        const float fx = x - xf, fy = y - yf, fz = z - zf;
        const int x0 = (int)xf, y0 = (int)yf, z0 = (int)zf;

        const float c000 = fetchv(vol, z0,     y0,     x0);
        const float c001 = fetchv(vol, z0,     y0,     x0 + 1);
        const float c010 = fetchv(vol, z0,     y0 + 1, x0);
        const float c011 = fetchv(vol, z0,     y0 + 1, x0 + 1);
        const float c100 = fetchv(vol, z0 + 1, y0,     x0);
        const float c101 = fetchv(vol, z0 + 1, y0,     x0 + 1);
        const float c110 = fetchv(vol, z0 + 1, y0 + 1, x0);
        const float c111 = fetchv(vol, z0 + 1, y0 + 1, x0 + 1);

        const float gx = 1.0f - fx, gy = 1.0f - fy, gz = 1.0f - fz;
        const float v00 = gx * c000 + fx * c001;
        const float v01 = gx * c010 + fx * c011;
        const float v10 = gx * c100 + fx * c101;
        const float v11 = gx * c110 + fx * c111;
        const float v0  = gy * v00 + fy * v01;
        const float v1  = gy * v10 + fy * v11;
        acc = fmaf(gz, v0, fmaf(fz, v1, acc));
    }

    out[idx] = acc * DT;
}

extern "C" void kernel_launch(void* const* d_in, const int* in_sizes, int n_in,
                              void* d_out, int out_size) {
    // Robust input binding: the angles array has 16 elements, the volume 16.7M.
    const float* img = (const float*)d_in[0];
    const float* ang = (const float*)d_in[1];
    if (n_in >= 2 && in_sizes[0] < in_sizes[1]) {
        img = (const float*)d_in[1];
        ang = (const float*)d_in[0];
    }
    float* out = (float*)d_out;

    const int total = NVIEW * NROW * NCOL;  // 393216
    const int threads = 256;
    const int blocks = (total + threads - 1) / threads;
    proj_kernel<<<blocks, threads>>>(img, ang, out);
}

// round 2
// speedup vs baseline: 1.5137x; 1.5137x over previous
#include <cuda_runtime.h>

// Cone-beam flat-panel forward projector, dual-layout L1-optimized.
// vol: [256,256,256] fp32 (z,y,x; x fastest). out: [16,64,384] fp32.

#define NCOL 384
#define NROW 64
#define NVIEW 16
#define NSAMP 256

// Transposed copy: g_volT[z][x][y] (y fastest). 64 MB static scratch.
__device__ float g_volT[256 * 256 * 256];

__global__ void __launch_bounds__(256)
transpose_kernel(const float* __restrict__ vol) {
    __shared__ float tile[32][33];
    const int z  = blockIdx.z;
    const int x0 = blockIdx.x * 32;
    const int y0 = blockIdx.y * 32;
    const int tx = threadIdx.x;        // 0..31
    const int ty = threadIdx.y;        // 0..7
    const float* src = vol    + (z << 16);
    float*       dst = g_volT + (z << 16);
    #pragma unroll
    for (int i = 0; i < 32; i += 8)
        tile[ty + i][tx] = src[((y0 + ty + i) << 8) | (x0 + tx)];
    __syncthreads();
    #pragma unroll
    for (int i = 0; i < 32; i += 8)
        dst[((x0 + ty + i) << 8) | (y0 + tx)] = tile[tx][ty + i];
}

// Slow-path fetch with per-corner bounds check. Layout: base[(z<<16)|(b<<8)|a].
__device__ __forceinline__ float fetchv(const float* __restrict__ base,
                                        int z, int b, int a) {
    if ((unsigned)a < 256u && (unsigned)b < 256u && (unsigned)z < 256u)
        return __ldg(base + ((z << 16) | (b << 8) | a));
    return 0.0f;
}

__global__ void __launch_bounds__(256)
proj_kernel(const float* __restrict__ vol,
            const float* __restrict__ angles,
            float* __restrict__ out) {
    const int idx = blockIdx.x * blockDim.x + threadIdx.x;
    const int total = NVIEW * NROW * NCOL;
    if (idx >= total) return;

    const int col  = idx % NCOL;
    const int tmp  = idx / NCOL;
    const int row  = tmp % NROW;
    const int view = tmp / NROW;

    const float DET_U = 1.2f, DET_V = 1.2f;
    const float ISO = 500.0f, SDD = 1000.0f;
    const float RAY_LEN = 1.7320508075688772f * 256.0f;  // sqrt(3)*256
    const float DT = RAY_LEN / (float)NSAMP;             // sqrt(3)

    const float beta = angles[view];
    const float cb = cosf(beta);
    const float sb = sinf(beta);

    const float u = ((float)col - NCOL * 0.5f + 0.5f) * DET_U;
    const float v = ((float)row - NROW * 0.5f + 0.5f) * DET_V;

    // source & unit ray direction
    const float sx = ISO * cb;
    const float sy = ISO * sb;
    float dx = -(SDD - ISO) * cb - u * sb - sx;
    float dy = -(SDD - ISO) * sb + u * cb - sy;
    float dz = v;
    const float inv = rsqrtf(dx * dx + dy * dy + dz * dz);
    dx *= inv; dy *= inv; dz *= inv;

    // Lane direction across a warp is the detector u-axis = (-sb, cb, 0).
    // Pick the layout whose contiguous axis matches the dominant component.
    const bool swp = fabsf(sb) < fabsf(cb);   // true -> lanes vary mostly in y
    const float* __restrict__ base = swp ? g_volT : vol;
    const float sA = swp ? sy : sx;           // 'a' = contiguous (fast) axis
    const float sB = swp ? sx : sy;
    const float dA = swp ? dy : dx;
    const float dB = swp ? dx : dy;

    const float t0 = ISO - RAY_LEN * 0.5f + 0.5f * DT;

    // Exact slab clip: sample contributes 0 unless every coord in (-128.5,128.5).
    float tmin = -1e30f, tmax = 1e30f;
    {
        const float s0[3] = {sA, sB, 0.0f};
        const float dd[3] = {dA, dB, dz};
        #pragma unroll
        for (int ax = 0; ax < 3; ++ax) {
            if (fabsf(dd[ax]) > 1e-12f) {
                const float r  = 1.0f / dd[ax];
                const float ta = (-128.5f - s0[ax]) * r;
                const float tb = ( 128.5f - s0[ax]) * r;
                tmin = fmaxf(tmin, fminf(ta, tb));
                tmax = fminf(tmax, fmaxf(ta, tb));
            } else if (s0[ax] <= -128.5f || s0[ax] >= 128.5f) {
                tmax = tmin - 1.0f;  // empty interval
            }
        }
    }
    int s_lo = (int)floorf((tmin - t0) / DT);
    int s_hi = (int)ceilf((tmax - t0) / DT) + 1;
    s_lo = max(s_lo, 0);
    s_hi = min(s_hi, NSAMP - 1);

    float acc = 0.0f;
    #pragma unroll 4
    for (int s = s_lo; s <= s_hi; ++s) {
        const float t = fmaf((float)s, DT, t0);
        const float a = fmaf(t, dA, sA) + 127.5f;
        const float b = fmaf(t, dB, sB) + 127.5f;
        const float z = fmaf(t, dz, 0.0f) + 127.5f;

        const float af = floorf(a), bf = floorf(b), zf = floorf(z);
        const float fa = a - af, fb = b - bf, fz = z - zf;
        const int a0 = (int)af, b0 = (int)bf, z0 = (int)zf;

        float c000, c001, c010, c011, c100, c101, c110, c111;
        if ((unsigned)a0 < 255u && (unsigned)b0 < 255u && (unsigned)z0 < 255u) {
            // interior: unpredicated, batched loads
            const float* p = base + ((z0 << 16) | (b0 << 8) | a0);
            c000 = __ldg(p);
            c001 = __ldg(p + 1);
            c010 = __ldg(p + 256);
            c011 = __ldg(p + 257);
            c100 = __ldg(p + 65536);
            c101 = __ldg(p + 65537);
            c110 = __ldg(p + 65536 + 256);
            c111 = __ldg(p + 65536 + 257);
        } else {
            c000 = fetchv(base, z0,     b0,     a0);
            c001 = fetchv(base, z0,     b0,     a0 + 1);
            c010 = fetchv(base, z0,     b0 + 1, a0);
            c011 = fetchv(base, z0,     b0 + 1, a0 + 1);
            c100 = fetchv(base, z0 + 1, b0,     a0);
            c101 = fetchv(base, z0 + 1, b0,     a0 + 1);
            c110 = fetchv(base, z0 + 1, b0 + 1, a0);
            c111 = fetchv(base, z0 + 1, b0 + 1, a0 + 1);
        }

        const float ga = 1.0f - fa, gb = 1.0f - fb, gz = 1.0f - fz;
        const float v00 = ga * c000 + fa * c001;
        const float v01 = ga * c010 + fa * c011;
        const float v10 = ga * c100 + fa * c101;
        const float v11 = ga * c110 + fa * c111;
        const float v0  = gb * v00 + fb * v01;
        const float v1  = gb * v10 + fb * v11;
        acc = fmaf(gz, v0, fmaf(fz, v1, acc));
    }

    out[idx] = acc * DT;
}

extern "C" void kernel_launch(void* const* d_in, const int* in_sizes, int n_in,
                              void* d_out, int out_size) {
    const float* img = (const float*)d_in[0];
    const float* ang = (const float*)d_in[1];
    if (n_in >= 2 && in_sizes[0] < in_sizes[1]) {
        img = (const float*)d_in[1];
        ang = (const float*)d_in[0];
    }
    float* out = (float*)d_out;

    // 1) build transposed copy (y-fastest)
    dim3 tb(32, 8, 1);
    dim3 tg(256 / 32, 256 / 32, 256);
    transpose_kernel<<<tg, tb>>>(img);

    // 2) project
    const int total = NVIEW * NROW * NCOL;  // 393216
    const int threads = 256;
    const int blocks = (total + threads - 1) / threads;
    proj_kernel<<<blocks, threads>>>(img, ang, out);
}

// round 3
// speedup vs baseline: 1.7298x; 1.1428x over previous
#include <cuda_runtime.h>

// Cone-beam flat-panel forward projector.
// Round-3 layout: volT[y][x][z] (z fastest). Warp lanes along detector rows (v),
// whose volume-space direction is pure z -> contiguous-axis lane spread for
// EVERY view angle.
// vol in: [256,256,256] fp32 (z,y,x; x fastest). out: [16,64,384] fp32.

#define NCOL 384
#define NROW 64
#define NVIEW 16
#define NSAMP 256

__device__ float g_volT[256 * 256 * 256];   // [y][x][z], z fastest (64 MB)

// z <-> x transpose within each y-plane, via shared tile.
__global__ void __launch_bounds__(256)
transpose_kernel(const float* __restrict__ vol) {
    __shared__ float tile[32][33];
    const int z0 = blockIdx.x * 32;
    const int x0 = blockIdx.y * 32;
    const int y  = blockIdx.z;
    const int tx = threadIdx.x;   // 0..31
    const int ty = threadIdx.y;   // 0..7

    // load: rows = z, lanes = x (coalesced on src x-fast layout)
    #pragma unroll
    for (int i = 0; i < 32; i += 8)
        tile[ty + i][tx] = vol[((z0 + ty + i) << 16) | (y << 8) | (x0 + tx)];
    __syncthreads();
    // store: rows = x, lanes = z (coalesced on dst z-fast layout)
    #pragma unroll
    for (int i = 0; i < 32; i += 8)
        g_volT[(y << 16) | ((x0 + ty + i) << 8) | (z0 + tx)] = tile[tx][ty + i];
}

// boundary-path fetch from ORIGINAL volume layout [z][y][x]
__device__ __forceinline__ float fetchv(const float* __restrict__ vol,
                                        int z, int y, int x) {
    if ((unsigned)x < 256u && (unsigned)y < 256u && (unsigned)z < 256u)
        return __ldg(vol + ((z << 16) | (y << 8) | x));
    return 0.0f;
}

__global__ void __launch_bounds__(256)
proj_kernel(const float* __restrict__ vol,
            const float* __restrict__ angles,
            float* __restrict__ out) {
    const int idx = blockIdx.x * blockDim.x + threadIdx.x;
    const int total = NVIEW * NROW * NCOL;
    if (idx >= total) return;

    // lanes vary ROW (detector v) -> pure-z spread across a warp
    const int row  = idx & 63;
    const int col  = (idx >> 6) % NCOL;
    const int view = idx / (64 * NCOL);

    const float DET_U = 1.2f, DET_V = 1.2f;
    const float ISO = 500.0f, SDD = 1000.0f;
    const float RAY_LEN = 1.7320508075688772f * 256.0f;  // sqrt(3)*256
    const float DT = RAY_LEN / (float)NSAMP;             // sqrt(3)

    const float beta = angles[view];
    const float cb = cosf(beta);
    const float sb = sinf(beta);

    const float u = ((float)col - NCOL * 0.5f + 0.5f) * DET_U;
    const float v = ((float)row - NROW * 0.5f + 0.5f) * DET_V;

    const float sx = ISO * cb;
    const float sy = ISO * sb;
    float dx = -(SDD - ISO) * cb - u * sb - sx;
    float dy = -(SDD - ISO) * sb + u * cb - sy;
    float dz = v;
    const float inv = rsqrtf(dx * dx + dy * dy + dz * dz);
    dx *= inv; dy *= inv; dz *= inv;

    const float t0 = ISO - RAY_LEN * 0.5f + 0.5f * DT;

    // exact slab clip: contribution is 0 unless every coord in (-128.5, 128.5)
    float tmin = -1e30f, tmax = 1e30f;
    {
        const float s0[3] = {sx, sy, 0.0f};
        const float dd[3] = {dx, dy, dz};
        #pragma unroll
        for (int ax = 0; ax < 3; ++ax) {
            if (fabsf(dd[ax]) > 1e-12f) {
                const float r  = 1.0f / dd[ax];
                const float ta = (-128.5f - s0[ax]) * r;
                const float tb = ( 128.5f - s0[ax]) * r;
                tmin = fmaxf(tmin, fminf(ta, tb));
                tmax = fminf(tmax, fmaxf(ta, tb));
            } else if (s0[ax] <= -128.5f || s0[ax] >= 128.5f) {
                tmax = tmin - 1.0f;
            }
        }
    }
    int s_lo = (int)floorf((tmin - t0) / DT);
    int s_hi = (int)ceilf((tmax - t0) / DT) + 1;
    s_lo = max(s_lo, 0);
    s_hi = min(s_hi, NSAMP - 1);

    float acc = 0.0f;
    #pragma unroll 4
    for (int s = s_lo; s <= s_hi; ++s) {
        const float t = fmaf((float)s, DT, t0);
        const float x = fmaf(t, dx, sx) + 127.5f;
        const float y = fmaf(t, dy, sy) + 127.5f;
        const float z = fmaf(t, dz, 0.0f) + 127.5f;

        const float xf = floorf(x), yf = floorf(y), zf = floorf(z);
        const float fx = x - xf, fy = y - yf, fz = z - zf;
        const int x0 = (int)xf, y0 = (int)yf, z0 = (int)zf;

        float c000, c001, c010, c011, c100, c101, c110, c111;
        if ((unsigned)x0 < 255u && (unsigned)y0 < 255u && (unsigned)z0 < 255u) {
            // interior: volT[y][x][z], z contiguous. (z0,z0+1) share a line.
            const float* p = g_volT + ((y0 << 16) | (x0 << 8) | z0);
            c000 = __ldg(p);                 // (z0,   y0,   x0)
            c100 = __ldg(p + 1);             // (z0+1, y0,   x0)
            c001 = __ldg(p + 256);           // (z0,   y0,   x0+1)
            c101 = __ldg(p + 257);           // (z0+1, y0,   x0+1)
            c010 = __ldg(p + 65536);         // (z0,   y0+1, x0)
            c110 = __ldg(p + 65537);
            c011 = __ldg(p + 65536 + 256);
            c111 = __ldg(p + 65536 + 257);
        } else {
            c000 = fetchv(vol, z0,     y0,     x0);
            c001 = fetchv(vol, z0,     y0,     x0 + 1);
            c010 = fetchv(vol, z0,     y0 + 1, x0);
            c011 = fetchv(vol, z0,     y0 + 1, x0 + 1);
            c100 = fetchv(vol, z0 + 1, y0,     x0);
            c101 = fetchv(vol, z0 + 1, y0,     x0 + 1);
            c110 = fetchv(vol, z0 + 1, y0 + 1, x0);
            c111 = fetchv(vol, z0 + 1, y0 + 1, x0 + 1);
        }

        const float gx = 1.0f - fx, gy = 1.0f - fy, gz = 1.0f - fz;
        const float v00 = gx * c000 + fx * c001;
        const float v01 = gx * c010 + fx * c011;
        const float v10 = gx * c100 + fx * c101;
        const float v11 = gx * c110 + fx * c111;
        const float v0  = gy * v00 + fy * v01;
        const float v1  = gy * v10 + fy * v11;
        acc = fmaf(gz, v0, fmaf(fz, v1, acc));
    }

    out[(view * NROW + row) * NCOL + col] = acc * DT;
}

extern "C" void kernel_launch(void* const* d_in, const int* in_sizes, int n_in,
                              void* d_out, int out_size) {
    const float* img = (const float*)d_in[0];
    const float* ang = (const float*)d_in[1];
    if (n_in >= 2 && in_sizes[0] < in_sizes[1]) {
        img = (const float*)d_in[1];
        ang = (const float*)d_in[0];
    }
    float* out = (float*)d_out;

    dim3 tb(32, 8, 1);
    dim3 tg(8, 8, 256);            // (z-tiles, x-tiles, y)
    transpose_kernel<<<tg, tb>>>(img);

    const int total = NVIEW * NROW * NCOL;  // 393216
    proj_kernel<<<(total + 255) / 256, 256>>>(img, ang, out);
}

// round 4
// speedup vs baseline: 2.7455x; 1.5872x over previous
#include <cuda_runtime.h>

// Cone-beam flat-panel forward projector.
// volT[y][x][z] (z fastest) + lanes along detector rows (v) => pure-z lane
// spread for every view. Hot loop is branch-free via inner/outer slab split.
// vol in: [256,256,256] fp32 (z,y,x). out: [16,64,384] fp32.

#define NCOL 384
#define NROW 64
#define NVIEW 16
#define NSAMP 256

__device__ float g_volT[256 * 256 * 256];   // [y][x][z], z fastest (64 MB)

__global__ void __launch_bounds__(256)
transpose_kernel(const float* __restrict__ vol) {
    __shared__ float tile[32][33];
    const int z0 = blockIdx.x * 32;
    const int x0 = blockIdx.y * 32;
    const int y  = blockIdx.z;
    const int tx = threadIdx.x;
    const int ty = threadIdx.y;
    #pragma unroll
    for (int i = 0; i < 32; i += 8)
        tile[ty + i][tx] = vol[((z0 + ty + i) << 16) | (y << 8) | (x0 + tx)];
    __syncthreads();
    #pragma unroll
    for (int i = 0; i < 32; i += 8)
        g_volT[(y << 16) | ((x0 + ty + i) << 8) | (z0 + tx)] = tile[tx][ty + i];
}

// checked fetch from volT layout [y][x][z]
__device__ __forceinline__ float fetchT(int z, int y, int x) {
    if ((unsigned)x < 256u && (unsigned)y < 256u && (unsigned)z < 256u)
        return __ldg(g_volT + ((y << 16) | (x << 8) | z));
    return 0.0f;
}

__device__ __forceinline__ float trilerp_checked(float x, float y, float z) {
    const float xf = floorf(x), yf = floorf(y), zf = floorf(z);
    const float fx = x - xf, fy = y - yf, fz = z - zf;
    const int x0 = (int)xf, y0 = (int)yf, z0 = (int)zf;
    const float c000 = fetchT(z0,     y0,     x0);
    const float c001 = fetchT(z0,     y0,     x0 + 1);
    const float c010 = fetchT(z0,     y0 + 1, x0);
    const float c011 = fetchT(z0,     y0 + 1, x0 + 1);
    const float c100 = fetchT(z0 + 1, y0,     x0);
    const float c101 = fetchT(z0 + 1, y0,     x0 + 1);
    const float c110 = fetchT(z0 + 1, y0 + 1, x0);
    const float c111 = fetchT(z0 + 1, y0 + 1, x0 + 1);
    const float gx = 1.0f - fx, gy = 1.0f - fy, gz = 1.0f - fz;
    const float v00 = gx * c000 + fx * c001;
    const float v01 = gx * c010 + fx * c011;
    const float v10 = gx * c100 + fx * c101;
    const float v11 = gx * c110 + fx * c111;
    const float v0  = gy * v00 + fy * v01;
    const float v1  = gy * v10 + fy * v11;
    return gz * v0 + fz * v1;
}

__global__ void __launch_bounds__(256)
proj_kernel(const float* __restrict__ angles,
            float* __restrict__ out) {
    const int idx = blockIdx.x * blockDim.x + threadIdx.x;
    const int total = NVIEW * NROW * NCOL;
    if (idx >= total) return;

    const int row  = idx & 63;               // lanes vary detector row (v) -> z
    const int col  = (idx >> 6) % NCOL;
    const int view = idx / (64 * NCOL);

    const float DET_U = 1.2f, DET_V = 1.2f;
    const float ISO = 500.0f, SDD = 1000.0f;
    const float RAY_LEN = 1.7320508075688772f * 256.0f;
    const float DT = RAY_LEN / (float)NSAMP;  // sqrt(3)

    const float beta = angles[view];
    const float cb = cosf(beta);
    const float sb = sinf(beta);

    const float u = ((float)col - NCOL * 0.5f + 0.5f) * DET_U;
    const float v = ((float)row - NROW * 0.5f + 0.5f) * DET_V;

    const float sx = ISO * cb;
    const float sy = ISO * sb;
    float dx = -(SDD - ISO) * cb - u * sb - sx;
    float dy = -(SDD - ISO) * sb + u * cb - sy;
    float dz = v;
    const float inv = rsqrtf(dx * dx + dy * dy + dz * dz);
    dx *= inv; dy *= inv; dz *= inv;

    const float t0 = ISO - RAY_LEN * 0.5f + 0.5f * DT;

    // Outer clip: contribution 0 unless all volume coords in (-128.5, 128.5).
    // Inner clip: cell fully interior when all coords in [-127.49, 127.49].
    float tmin = -1e30f, tmax = 1e30f;     // outer
    float t2mn = -1e30f, t2mx = 1e30f;     // inner
    {
        const float s0[3] = {sx, sy, 0.0f};
        const float dd[3] = {dx, dy, dz};
        #pragma unroll
        for (int ax = 0; ax < 3; ++ax) {
            if (fabsf(dd[ax]) > 1e-12f) {
                const float r = 1.0f / dd[ax];
                float ta = (-128.5f - s0[ax]) * r;
                float tb = ( 128.5f - s0[ax]) * r;
                tmin = fmaxf(tmin, fminf(ta, tb));
                tmax = fminf(tmax, fmaxf(ta, tb));
                ta = (-127.49f - s0[ax]) * r;
                tb = ( 127.49f - s0[ax]) * r;
                t2mn = fmaxf(t2mn, fminf(ta, tb));
                t2mx = fminf(t2mx, fmaxf(ta, tb));
            } else {
                if (s0[ax] <= -128.5f  || s0[ax] >= 128.5f)  tmax = tmin - 1.0f;
                if (s0[ax] <  -127.49f || s0[ax] >  127.49f) t2mx = t2mn - 1.0f;
            }
        }
    }
    int s_lo = max((int)floorf((tmin - t0) / DT), 0);
    int s_hi = min((int)ceilf ((tmax - t0) / DT) + 1, NSAMP - 1);
    int i_lo = max((int)ceilf ((t2mn - t0) / DT), s_lo);
    int i_hi = min((int)floorf((t2mx - t0) / DT), s_hi);
    if (i_lo > i_hi) { i_lo = s_hi + 1; i_hi = s_hi; }   // empty interior

    // per-sample-index linear coordinate coefficients (exact, non-accumulating)
    const float ax0 = fmaf(t0, dx, sx) + 127.5f;   // x at s=0
    const float ay0 = fmaf(t0, dy, sy) + 127.5f;
    const float az0 = fmaf(t0, dz, 0.0f) + 127.5f;
    const float axs = DT * dx, ays = DT * dy, azs = DT * dz;

    float acc = 0.0f;

    // head boundary (checked)
    for (int s = s_lo; s < i_lo; ++s) {
        const float fs = (float)s;
        acc += trilerp_checked(fmaf(fs, axs, ax0), fmaf(fs, ays, ay0),
                               fmaf(fs, azs, az0));
    }

    // interior hot loop: no bounds logic at all
    #pragma unroll 4
    for (int s = i_lo; s <= i_hi; ++s) {
        const float fs = (float)s;
        const float x = fmaf(fs, axs, ax0);
        const float y = fmaf(fs, ays, ay0);
        const float z = fmaf(fs, azs, az0);

        const float xf = floorf(x), yf = floorf(y), zf = floorf(z);
        const float fx = x - xf, fy = y - yf, fz = z - zf;
        const int x0 = (int)xf, y0 = (int)yf, z0 = (int)zf;

        const float* p = g_volT + ((y0 << 16) | (x0 << 8) | z0);
        const float c000 = __ldg(p);
        const float c100 = __ldg(p + 1);
        const float c001 = __ldg(p + 256);
        const float c101 = __ldg(p + 257);
        const float c010 = __ldg(p + 65536);
        const float c110 = __ldg(p + 65537);
        const float c011 = __ldg(p + 65536 + 256);
        const float c111 = __ldg(p + 65536 + 257);

        const float gx = 1.0f - fx, gy = 1.0f - fy, gz = 1.0f - fz;
        const float v00 = gx * c000 + fx * c001;
        const float v01 = gx * c010 + fx * c011;
        const float v10 = gx * c100 + fx * c101;
        const float v11 = gx * c110 + fx * c111;
        const float v0  = gy * v00 + fy * v01;
        const float v1  = gy * v10 + fy * v11;
        acc = fmaf(gz, v0, fmaf(fz, v1, acc));
    }

    // tail boundary (checked)
    for (int s = i_hi + 1; s <= s_hi; ++s) {
        const float fs = (float)s;
        acc += trilerp_checked(fmaf(fs, axs, ax0), fmaf(fs, ays, ay0),
                               fmaf(fs, azs, az0));
    }

    out[(view * NROW + row) * NCOL + col] = acc * DT;
}

extern "C" void kernel_launch(void* const* d_in, const int* in_sizes, int n_in,
                              void* d_out, int out_size) {
    const float* img = (const float*)d_in[0];
    const float* ang = (const float*)d_in[1];
    if (n_in >= 2 && in_sizes[0] < in_sizes[1]) {
        img = (const float*)d_in[1];
        ang = (const float*)d_in[0];
    }
    float* out = (float*)d_out;

    dim3 tb(32, 8, 1);
    dim3 tg(8, 8, 256);
    transpose_kernel<<<tg, tb>>>(img);

    const int total = NVIEW * NROW * NCOL;
    proj_kernel<<<(total + 255) / 256, 256>>>(ang, out);
}

// round 7
// speedup vs baseline: 3.0002x; 1.0928x over previous
#include <cuda_runtime.h>
#include <cstdint>

// Cone-beam flat-panel forward projector, round 7.
// g_volP[y][x][z] = (vol[z,y,x], vol[z+1,y,x]) pairs (z fastest, 128 MB).
// Lanes along detector rows (v) => pure-z lane spread for every view angle.
// Hot loop: 4x LDG.64 + packed f32x2 bilinear + packed accumulator.
// FIX vs round 5/6: u11 offset is +65792 (= y-stride + x-stride in PAIR units),
// not +65537 (which was correct only for the old scalar layout).
// vol in: [256,256,256] fp32 (z,y,x). out: [16,64,384] fp32.

#define NCOL 384
#define NROW 64
#define NVIEW 16
#define NSAMP 256

__device__ unsigned long long g_volP[256 * 256 * 256];  // [y][x][z] pairs, 128 MB

// ---- packed f32x2 helpers ----
__device__ __forceinline__ unsigned long long pk2(float lo, float hi) {
    unsigned long long r;
    asm("mov.b64 %0, {%1, %2};"
        : "=l"(r) : "r"(__float_as_uint(lo)), "r"(__float_as_uint(hi)));
    return r;
}
__device__ __forceinline__ unsigned long long mul2(unsigned long long a,
                                                   unsigned long long b) {
    unsigned long long r;
    asm("mul.rn.f32x2 %0, %1, %2;" : "=l"(r) : "l"(a), "l"(b));
    return r;
}
__device__ __forceinline__ unsigned long long fma2(unsigned long long a,
                                                   unsigned long long b,
                                                   unsigned long long c) {
    unsigned long long r;
    asm("fma.rn.f32x2 %0, %1, %2, %3;" : "=l"(r) : "l"(a), "l"(b), "l"(c));
    return r;
}
__device__ __forceinline__ void unpk2(unsigned long long v, float& lo, float& hi) {
    unsigned int ulo, uhi;
    asm("mov.b64 {%0, %1}, %2;" : "=r"(ulo), "=r"(uhi) : "l"(v));
    lo = __uint_as_float(ulo);
    hi = __uint_as_float(uhi);
}

// transpose + z-pair build: vol[z][y][x] -> g_volP[y][x][z] = (v[z], v[z+1])
__global__ void __launch_bounds__(256)
transpose_pair_kernel(const float* __restrict__ vol) {
    __shared__ float ts[33][33];               // [local z 0..32][local x 0..31]
    const int z0 = blockIdx.x * 32;
    const int x0 = blockIdx.y * 32;
    const int y  = blockIdx.z;
    const int tx = threadIdx.x;                // 0..31
    const int ty = threadIdx.y;                // 0..7

    #pragma unroll
    for (int i = 0; i < 32; i += 8)
        ts[ty + i][tx] = vol[((z0 + ty + i) << 16) | (y << 8) | (x0 + tx)];
    if (ty == 0) {
        const int z = z0 + 32;
        ts[32][tx] = (z < 256) ? vol[(z << 16) | (y << 8) | (x0 + tx)] : 0.0f;
    }
    __syncthreads();

    #pragma unroll
    for (int i = 0; i < 32; i += 8) {
        const unsigned long long pr =
            ((unsigned long long)__float_as_uint(ts[tx + 1][ty + i]) << 32) |
            (unsigned long long)__float_as_uint(ts[tx][ty + i]);
        g_volP[(y << 16) | ((x0 + ty + i) << 8) | (z0 + tx)] = pr;
    }
}

// checked scalar fetch (boundary path): lo word of pair = vol[z,y,x]
__device__ __forceinline__ float fetchS(int z, int y, int x) {
    if ((unsigned)x < 256u && (unsigned)y < 256u && (unsigned)z < 256u) {
        const unsigned long long p = __ldg(g_volP + ((y << 16) | (x << 8) | z));
        return __uint_as_float((unsigned int)p);
    }
    return 0.0f;
}

__device__ __forceinline__ float trilerp_checked(float x, float y, float z) {
    const float xf = floorf(x), yf = floorf(y), zf = floorf(z);
    const float fx = x - xf, fy = y - yf, fz = z - zf;
    const int x0 = (int)xf, y0 = (int)yf, z0 = (int)zf;
    const float c000 = fetchS(z0,     y0,     x0);
    const float c001 = fetchS(z0,     y0,     x0 + 1);
    const float c010 = fetchS(z0,     y0 + 1, x0);
    const float c011 = fetchS(z0,     y0 + 1, x0 + 1);
    const float c100 = fetchS(z0 + 1, y0,     x0);
    const float c101 = fetchS(z0 + 1, y0,     x0 + 1);
    const float c110 = fetchS(z0 + 1, y0 + 1, x0);
    const float c111 = fetchS(z0 + 1, y0 + 1, x0 + 1);
    const float gx = 1.0f - fx, gy = 1.0f - fy, gz = 1.0f - fz;
    const float v00 = gx * c000 + fx * c001;
    const float v01 = gx * c010 + fx * c011;
    const float v10 = gx * c100 + fx * c101;
    const float v11 = gx * c110 + fx * c111;
    const float v0  = gy * v00 + fy * v01;
    const float v1  = gy * v10 + fy * v11;
    return gz * v0 + fz * v1;
}

__global__ void __launch_bounds__(256)
proj_kernel(const float* __restrict__ angles,
            float* __restrict__ out) {
    const int idx = blockIdx.x * blockDim.x + threadIdx.x;
    const int total = NVIEW * NROW * NCOL;
    if (idx >= total) return;

    const int row  = idx & 63;                 // lanes vary detector row -> z
    const int col  = (idx >> 6) % NCOL;
    const int view = idx / (64 * NCOL);

    const float DET_U = 1.2f, DET_V = 1.2f;
    const float ISO = 500.0f, SDD = 1000.0f;
    const float RAY_LEN = 1.7320508075688772f * 256.0f;
    const float DT = RAY_LEN / (float)NSAMP;   // sqrt(3)

    const float beta = angles[view];
    const float cb = cosf(beta);
    const float sb = sinf(beta);

    const float u = ((float)col - NCOL * 0.5f + 0.5f) * DET_U;
    const float v = ((float)row - NROW * 0.5f + 0.5f) * DET_V;

    const float sx = ISO * cb;
    const float sy = ISO * sb;
    float dx = -(SDD - ISO) * cb - u * sb - sx;
    float dy = -(SDD - ISO) * sb + u * cb - sy;
    float dz = v;
    const float inv = rsqrtf(dx * dx + dy * dy + dz * dz);
    dx *= inv; dy *= inv; dz *= inv;

    const float t0 = ISO - RAY_LEN * 0.5f + 0.5f * DT;

    // outer clip (all coords in (-128.5,128.5)) and inner fully-interior clip
    float tmin = -1e30f, tmax = 1e30f;
    float t2mn = -1e30f, t2mx = 1e30f;
    {
        const float s0[3] = {sx, sy, 0.0f};
        const float dd[3] = {dx, dy, dz};
        #pragma unroll
        for (int ax = 0; ax < 3; ++ax) {
            if (fabsf(dd[ax]) > 1e-12f) {
                const float r = 1.0f / dd[ax];
                float ta = (-128.5f - s0[ax]) * r;
                float tb = ( 128.5f - s0[ax]) * r;
                tmin = fmaxf(tmin, fminf(ta, tb));
                tmax = fminf(tmax, fmaxf(ta, tb));
                ta = (-127.49f - s0[ax]) * r;
                tb = ( 127.49f - s0[ax]) * r;
                t2mn = fmaxf(t2mn, fminf(ta, tb));
                t2mx = fminf(t2mx, fmaxf(ta, tb));
            } else {
                if (s0[ax] <= -128.5f  || s0[ax] >= 128.5f)  tmax = tmin - 1.0f;
                if (s0[ax] <  -127.49f || s0[ax] >  127.49f) t2mx = t2mn - 1.0f;
            }
        }
    }
    int s_lo = max((int)floorf((tmin - t0) / DT), 0);
    int s_hi = min((int)ceilf ((tmax - t0) / DT) + 1, NSAMP - 1);
    int i_lo = max((int)ceilf ((t2mn - t0) / DT), s_lo);
    int i_hi = min((int)floorf((t2mx - t0) / DT), s_hi);
    if (i_lo > i_hi) { i_lo = s_hi + 1; i_hi = s_hi; }

    const float ax0 = fmaf(t0, dx, sx) + 127.5f;
    const float ay0 = fmaf(t0, dy, sy) + 127.5f;
    const float az0 = fmaf(t0, dz, 0.0f) + 127.5f;
    const float axs = DT * dx, ays = DT * dy, azs = DT * dz;

    float acc = 0.0f;

    // head boundary (checked, scalar)
    for (int s = s_lo; s < i_lo; ++s) {
        const float fs = (float)s;
        acc += trilerp_checked(fmaf(fs, axs, ax0), fmaf(fs, ays, ay0),
                               fmaf(fs, azs, az0));
    }

    // interior hot loop: packed accumulator (lo += gz*v.lo, hi += fz*v.hi)
    unsigned long long acc2 = 0ull;
    #pragma unroll 4
    for (int s = i_lo; s <= i_hi; ++s) {
        const float fs = (float)s;
        const float x = fmaf(fs, axs, ax0);
        const float y = fmaf(fs, ays, ay0);
        const float z = fmaf(fs, azs, az0);

        const float xf = floorf(x), yf = floorf(y), zf = floorf(z);
        const float fx = x - xf, fy = y - yf, fz = z - zf;
        const int x0 = (int)xf, y0 = (int)yf, z0 = (int)zf;

        // pair-layout strides: z=1, x=256, y=65536 (in PAIR elements)
        const unsigned long long* p = g_volP + ((y0 << 16) | (x0 << 8) | z0);
        const unsigned long long u00 = __ldg(p);                  // (y0,  x0  )
        const unsigned long long u01 = __ldg(p + 256);            // (y0,  x0+1)
        const unsigned long long u10 = __ldg(p + 65536);          // (y0+1,x0  )
        const unsigned long long u11 = __ldg(p + 65536 + 256);    // (y0+1,x0+1)

        const float gx = 1.0f - fx, gy = 1.0f - fy, gz = 1.0f - fz;
        const unsigned long long gx2 = pk2(gx, gx), fx2 = pk2(fx, fx);
        const unsigned long long gy2 = pk2(gy, gy), fy2 = pk2(fy, fy);

        unsigned long long v0 = mul2(gx2, u00); v0 = fma2(fx2, u01, v0);
        unsigned long long v1 = mul2(gx2, u10); v1 = fma2(fx2, u11, v1);
        unsigned long long vv = mul2(gy2, v0);  vv = fma2(fy2, v1, vv);

        acc2 = fma2(pk2(gz, fz), vv, acc2);
    }
    {
        float alo, ahi;
        unpk2(acc2, alo, ahi);
        acc += alo + ahi;
    }

    // tail boundary (checked, scalar)
    for (int s = i_hi + 1; s <= s_hi; ++s) {
        const float fs = (float)s;
        acc += trilerp_checked(fmaf(fs, axs, ax0), fmaf(fs, ays, ay0),
                               fmaf(fs, azs, az0));
    }

    out[(view * NROW + row) * NCOL + col] = acc * DT;
}

extern "C" void kernel_launch(void* const* d_in, const int* in_sizes, int n_in,
                              void* d_out, int out_size) {
    const float* img = (const float*)d_in[0];
    const float* ang = (const float*)d_in[1];
    if (n_in >= 2 && in_sizes[0] < in_sizes[1]) {
        img = (const float*)d_in[1];
        ang = (const float*)d_in[0];
    }
    float* out = (float*)d_out;

    dim3 tb(32, 8, 1);
    dim3 tg(8, 8, 256);            // (z-tiles, x-tiles, y)
    transpose_pair_kernel<<<tg, tb>>>(img);

    const int total = NVIEW * NROW * NCOL;
    proj_kernel<<<(total + 255) / 256, 256>>>(ang, out);
}